// round 2
// baseline (speedup 1.0000x reference)
#include <cuda_runtime.h>

// Problem constants (fixed shapes)
#define NNZ     4194304
#define DENSE   16
#define DIMLOG  13
#define DIMSZ   8192
#define CELLS   67108864u          // 2^26
#define WORDS   2097152u           // CELLS / 32
#define C1_BLOCKS 2048
#define WPT     4                  // words per thread in popcount/compact kernels

// Scratch (static device globals; no allocation allowed)
__device__ __align__(16) unsigned g_bitmap[WORDS];    // occupancy bits
__device__ __align__(16) unsigned g_dup[WORDS];       // "has >=2 contributors" bits
__device__ __align__(16) unsigned g_wordoff[WORDS];   // exclusive prefix of popcounts
__device__ unsigned g_blocksums[C1_BLOCKS];
__device__ unsigned g_total;

// ---------------------------------------------------------------------------
// Block-wide exclusive scan (256 threads). Returns exclusive prefix of v,
// sets blocktotal to the block-wide sum. All 256 threads must participate.
__device__ __forceinline__ unsigned block_exscan(unsigned v, unsigned& blocktotal) {
    __shared__ unsigned warp_sums[8];
    __shared__ unsigned warp_off[8];
    unsigned lane = threadIdx.x & 31u, wid = threadIdx.x >> 5;
    unsigned x = v;
#pragma unroll
    for (int d = 1; d < 32; d <<= 1) {
        unsigned y = __shfl_up_sync(0xffffffffu, x, d);
        if ((int)lane >= d) x += y;
    }
    if (lane == 31) warp_sums[wid] = x;
    __syncthreads();
    if (threadIdx.x < 8) {
        unsigned s = warp_sums[threadIdx.x];
        unsigned inc = s;
#pragma unroll
        for (int d = 1; d < 8; d <<= 1) {
            unsigned y = __shfl_up_sync(0xffu, inc, d);
            if ((int)threadIdx.x >= d) inc += y;
        }
        warp_off[threadIdx.x] = inc - s;   // exclusive
    }
    __syncthreads();
    blocktotal = warp_off[7] + warp_sums[7];
    return warp_off[wid] + (x - v);
}

// ---------------------------------------------------------------------------
// Z: zero both bitmaps (16MB) with 16B stores
__global__ void k_zero() {
    unsigned i = blockIdx.x * blockDim.x + threadIdx.x;
    uint4 z = {0u, 0u, 0u, 0u};
    if (i < WORDS / 4) ((uint4*)g_bitmap)[i] = z;
    else               ((uint4*)g_dup)[i - WORDS / 4] = z;
}

// B: mark occupancy + duplicate bits (all atomics land in L2: 16MB region)
__global__ void k_mark(const int* __restrict__ idx) {
    unsigned i = blockIdx.x * blockDim.x + threadIdx.x;
    unsigned flat = ((unsigned)idx[i] << DIMLOG) | (unsigned)idx[NNZ + i];
    unsigned w = flat >> 5, m = 1u << (flat & 31u);
    unsigned old = atomicOr(&g_bitmap[w], m);
    if (old & m) atomicOr(&g_dup[w], m);
}

// C1: per-block popcount sums
__global__ void k_popcnt_sums() {
    unsigned base = blockIdx.x * (256u * WPT) + threadIdx.x * WPT;
    unsigned s = 0;
#pragma unroll
    for (int j = 0; j < WPT; j++) s += __popc(g_bitmap[base + j]);
    unsigned tot;
    (void)block_exscan(s, tot);
    if (threadIdx.x == 0) g_blocksums[blockIdx.x] = tot;
}

// C2: exclusive scan of the 2048 block sums (single block, 256 thr x 8 elems)
__global__ void k_scan_blocks(float* __restrict__ out) {
    int t = threadIdx.x;
    unsigned a[8];
    unsigned s = 0;
#pragma unroll
    for (int j = 0; j < 8; j++) { a[j] = g_blocksums[t * 8 + j]; s += a[j]; }
    unsigned tot;
    unsigned ex = block_exscan(s, tot);
    unsigned run = ex;
#pragma unroll
    for (int j = 0; j < 8; j++) { unsigned v = a[j]; g_blocksums[t * 8 + j] = run; run += v; }
    if (t == 0) {
        g_total = tot;
        out[(size_t)2 * NNZ + (size_t)NNZ * DENSE] = (float)tot;  // n_unique
    }
}

// C3: write per-word exclusive offsets + compact sorted unique indices to out
__global__ void k_compact(float* __restrict__ out) {
    unsigned base = blockIdx.x * (256u * WPT) + threadIdx.x * WPT;
    unsigned words[WPT];
    unsigned s = 0;
#pragma unroll
    for (int j = 0; j < WPT; j++) { words[j] = g_bitmap[base + j]; s += __popc(words[j]); }
    unsigned tot;
    unsigned ex = block_exscan(s, tot);
    unsigned off = g_blocksums[blockIdx.x] + ex;
    float* out0 = out;
    float* out1 = out + NNZ;
#pragma unroll
    for (int j = 0; j < WPT; j++) {
        unsigned w = base + j;
        g_wordoff[w] = off;
        unsigned v = words[j];
        while (v) {
            unsigned b = (unsigned)__ffs(v) - 1u;
            v &= v - 1u;
            unsigned cell = (w << 5) | b;
            out0[off] = (float)(cell >> DIMLOG);
            out1[off] = (float)(cell & (DIMSZ - 1));
            off++;
        }
    }
}

// T: padded tail — indices (8192, 0) per reference fill, values zero
__global__ void k_tail(float* __restrict__ out) {
    unsigned slot = blockIdx.x * blockDim.x + threadIdx.x;
    unsigned nu = g_total;
    if (slot < nu) return;
    out[slot] = 8192.0f;
    out[NNZ + slot] = 0.0f;
    float4* v = (float4*)(out + (size_t)2 * NNZ + (size_t)slot * DENSE);
    float4 z = {0.f, 0.f, 0.f, 0.f};
    v[0] = z; v[1] = z; v[2] = z; v[3] = z;
}

// D2: zero value rows that have multiple contributors (so atomics accumulate)
__global__ void k_zerodup(float* __restrict__ out) {
    unsigned w = blockIdx.x * blockDim.x + threadIdx.x;
    unsigned d = g_dup[w];
    if (!d) return;
    unsigned bm = g_bitmap[w];
    unsigned base = g_wordoff[w];
    float* vout = out + (size_t)2 * NNZ;
    while (d) {
        unsigned b = (unsigned)__ffs(d) - 1u;
        d &= d - 1u;
        unsigned slot = base + __popc(bm & ((1u << b) - 1u));
        float4* v = (float4*)(vout + (size_t)slot * DENSE);
        float4 z = {0.f, 0.f, 0.f, 0.f};
        v[0] = z; v[1] = z; v[2] = z; v[3] = z;
    }
}

// E: scatter/accumulate values into coalesced rows.
// 97% of rows have a single contributor -> plain STG.128 x4 (no atomics).
__global__ void k_scatter(const int* __restrict__ idx,
                          const float* __restrict__ vals,
                          float* __restrict__ out) {
    unsigned i = blockIdx.x * blockDim.x + threadIdx.x;
    unsigned flat = ((unsigned)idx[i] << DIMLOG) | (unsigned)idx[NNZ + i];
    unsigned w = flat >> 5, b = flat & 31u;
    unsigned bm = g_bitmap[w];
    unsigned slot = g_wordoff[w] + __popc(bm & ((1u << b) - 1u));
    const float4* src = (const float4*)(vals + (size_t)i * DENSE);
    float4 v0 = src[0], v1 = src[1], v2 = src[2], v3 = src[3];
    float* dst = out + (size_t)2 * NNZ + (size_t)slot * DENSE;
    if ((g_dup[w] >> b) & 1u) {
        atomicAdd(dst + 0,  v0.x); atomicAdd(dst + 1,  v0.y);
        atomicAdd(dst + 2,  v0.z); atomicAdd(dst + 3,  v0.w);
        atomicAdd(dst + 4,  v1.x); atomicAdd(dst + 5,  v1.y);
        atomicAdd(dst + 6,  v1.z); atomicAdd(dst + 7,  v1.w);
        atomicAdd(dst + 8,  v2.x); atomicAdd(dst + 9,  v2.y);
        atomicAdd(dst + 10, v2.z); atomicAdd(dst + 11, v2.w);
        atomicAdd(dst + 12, v3.x); atomicAdd(dst + 13, v3.y);
        atomicAdd(dst + 14, v3.z); atomicAdd(dst + 15, v3.w);
    } else {
        float4* d4 = (float4*)dst;
        d4[0] = v0; d4[1] = v1; d4[2] = v2; d4[3] = v3;
    }
}

// ---------------------------------------------------------------------------
extern "C" void kernel_launch(void* const* d_in, const int* in_sizes, int n_in,
                              void* d_out, int out_size) {
    (void)in_sizes; (void)n_in; (void)out_size;
    const int*   idx  = (const int*)d_in[0];    // [2, NNZ] int32
    const float* vals = (const float*)d_in[1];  // [NNZ, 16] f32
    float* out = (float*)d_out;                 // [2*NNZ + NNZ*16 + 1] f32

    k_zero       <<<(WORDS / 4 * 2) / 256, 256>>>();
    k_mark       <<<NNZ / 256,            256>>>(idx);
    k_popcnt_sums<<<C1_BLOCKS,            256>>>();
    k_scan_blocks<<<1,                    256>>>(out);
    k_compact    <<<C1_BLOCKS,            256>>>(out);
    k_tail       <<<NNZ / 256,            256>>>(out);
    k_zerodup    <<<WORDS / 256,          256>>>(out);
    k_scatter    <<<NNZ / 256,            256>>>(idx, vals, out);
}

// round 3
// speedup vs baseline: 1.1018x; 1.1018x over previous
#include <cuda_runtime.h>

#define NNZ     4194304
#define DENSE   16
#define DIMLOG  13
#define DIMSZ   8192
#define WORDS   2097152u           // 2^26 cells / 32
#define SCAN_BLOCKS 2048
#define SCAN_WPT 4                 // words per thread in the scan kernel

// Interleaved per-word metadata: x=occupancy bits, y=dup bits, z=exclusive
// slot offset of bit 0, w=pad. One 16B load (1 sector) serves the scatter.
__device__ __align__(16) uint4 g_meta[WORDS];
__device__ unsigned g_desc[SCAN_BLOCKS];   // decoupled-lookback descriptors
__device__ unsigned g_ticket;
__device__ unsigned g_total;

// ---------------------------------------------------------------------------
// Block-wide exclusive scan (256 threads).
__device__ __forceinline__ unsigned block_exscan(unsigned v, unsigned& blocktotal) {
    __shared__ unsigned warp_sums[8];
    __shared__ unsigned warp_off[8];
    unsigned lane = threadIdx.x & 31u, wid = threadIdx.x >> 5;
    unsigned x = v;
#pragma unroll
    for (int d = 1; d < 32; d <<= 1) {
        unsigned y = __shfl_up_sync(0xffffffffu, x, d);
        if ((int)lane >= d) x += y;
    }
    if (lane == 31) warp_sums[wid] = x;
    __syncthreads();
    if (threadIdx.x < 8) {
        unsigned s = warp_sums[threadIdx.x];
        unsigned inc = s;
#pragma unroll
        for (int d = 1; d < 8; d <<= 1) {
            unsigned y = __shfl_up_sync(0xffu, inc, d);
            if ((int)threadIdx.x >= d) inc += y;
        }
        warp_off[threadIdx.x] = inc - s;
    }
    __syncthreads();
    blocktotal = warp_off[7] + warp_sums[7];
    return warp_off[wid] + (x - v);
}

// ---------------------------------------------------------------------------
// Z: zero metadata (32MB) + lookback descriptors + ticket
__global__ void k_zero() {
    unsigned i = blockIdx.x * 256u + threadIdx.x;
    uint4 z = {0u, 0u, 0u, 0u};
    if (i < WORDS)                      g_meta[i] = z;
    else if (i < WORDS + SCAN_BLOCKS/4) ((uint4*)g_desc)[i - WORDS] = z;
    else if (i == WORDS + SCAN_BLOCKS/4) g_ticket = 0u;
}

// B: mark occupancy + duplicate bits (atomics land in L2-resident 32MB region)
__global__ void k_mark(const int* __restrict__ idx) {
    unsigned i = blockIdx.x * 256u + threadIdx.x;
    unsigned flat = ((unsigned)__ldcs(idx + i) << DIMLOG) | (unsigned)__ldcs(idx + NNZ + i);
    unsigned w = flat >> 5, m = 1u << (flat & 31u);
    unsigned old = atomicOr(&g_meta[w].x, m);
    if (old & m) atomicOr(&g_meta[w].y, m);
}

// S: single-pass scan (decoupled lookback) + compact unique indices
//    + store per-word offsets + zero dup value rows + write n_unique.
__global__ void k_scan_compact(float* __restrict__ out) {
    __shared__ unsigned sh_lbid, sh_prefix;
    unsigned tid = threadIdx.x;
    if (tid == 0) sh_lbid = atomicAdd(&g_ticket, 1u);
    __syncthreads();
    unsigned lbid = sh_lbid;
    unsigned base = lbid * (256u * SCAN_WPT) + tid * SCAN_WPT;

    uint4 mt[SCAN_WPT];
    unsigned s = 0;
#pragma unroll
    for (int j = 0; j < SCAN_WPT; j++) { mt[j] = g_meta[base + j]; s += __popc(mt[j].x); }
    unsigned tot;
    unsigned ex = block_exscan(s, tot);

    // Publish aggregate, then warp-parallel lookback for the exclusive prefix.
    if (tid < 32) {
        if (tid == 0) atomicExch(&g_desc[lbid], (tot << 2) | (lbid == 0 ? 2u : 1u));
        unsigned prefix = 0;
        if (lbid > 0) {
            int look = (int)lbid - 1;
            unsigned running = 0;
            while (true) {
                int j = look - 31 + (int)tid;
                unsigned d;
                if (j < 0) d = 2u;  // virtual prefix 0
                else {
                    do { d = *((volatile unsigned*)(g_desc + j)); } while ((d & 3u) == 0u);
                }
                unsigned ball = __ballot_sync(0xffffffffu, (d & 3u) == 2u);
                if (ball) {
                    int hi = 31 - __clz(ball);
                    unsigned contrib = ((int)tid >= hi) ? (d >> 2) : 0u;
                    running += __reduce_add_sync(0xffffffffu, contrib);
                    break;
                } else {
                    running += __reduce_add_sync(0xffffffffu, d >> 2);
                    look -= 32;
                }
            }
            prefix = running;
            if (tid == 0) atomicExch(&g_desc[lbid], ((prefix + tot) << 2) | 2u);
        }
        if (tid == 0) sh_prefix = prefix;
    }
    __syncthreads();

    unsigned off = sh_prefix + ex;
    if (lbid == SCAN_BLOCKS - 1 && tid == 0) {
        unsigned nu = sh_prefix + tot;
        g_total = nu;
        out[(size_t)2 * NNZ + (size_t)NNZ * DENSE] = (float)nu;
    }

    float* out0 = out;
    float* out1 = out + NNZ;
    float* vout = out + (size_t)2 * NNZ;
#pragma unroll
    for (int j = 0; j < SCAN_WPT; j++) {
        unsigned w = base + j;
        g_meta[w].z = off;                       // per-word exclusive offset
        unsigned bm = mt[j].x, dup = mt[j].y;
        unsigned o = off;
        unsigned v = bm;
        while (v) {
            unsigned b = (unsigned)__ffs(v) - 1u;
            v &= v - 1u;
            unsigned cell = (w << 5) | b;
            __stcs(out0 + o, (float)(cell >> DIMLOG));
            __stcs(out1 + o, (float)(cell & (DIMSZ - 1)));
            if ((dup >> b) & 1u) {               // pre-zero rows that accumulate
                float4* p = (float4*)(vout + (size_t)o * DENSE);
                float4 z = {0.f, 0.f, 0.f, 0.f};
                __stcs(p + 0, z); __stcs(p + 1, z); __stcs(p + 2, z); __stcs(p + 3, z);
            }
            o++;
        }
        off = o;
    }
}

// T: padded tail — indices (8192, 0), zero values
__global__ void k_tail(float* __restrict__ out) {
    unsigned slot = blockIdx.x * 256u + threadIdx.x;
    if (slot < g_total) return;
    __stcs(out + slot, 8192.0f);
    __stcs(out + NNZ + slot, 0.0f);
    float4* v = (float4*)(out + (size_t)2 * NNZ + (size_t)slot * DENSE);
    float4 z = {0.f, 0.f, 0.f, 0.f};
    __stcs(v + 0, z); __stcs(v + 1, z); __stcs(v + 2, z); __stcs(v + 3, z);
}

// E: scatter values. 4 threads per row (one float4 each); slot computed once
// per row by lanes 0..7 and broadcast. 97% of rows: plain streaming STG.128.
__global__ void k_scatter(const int* __restrict__ idx,
                          const float* __restrict__ vals,
                          float* __restrict__ out) {
    unsigned t = blockIdx.x * 256u + threadIdx.x;
    unsigned lane = threadIdx.x & 31u;
    unsigned warpRow0 = (t & ~31u) >> 2;       // first of this warp's 8 rows

    unsigned packed = 0;
    if (lane < 8) {
        unsigned r = warpRow0 + lane;
        unsigned flat = ((unsigned)__ldg(idx + r) << DIMLOG) | (unsigned)__ldg(idx + NNZ + r);
        unsigned w = flat >> 5, b = flat & 31u;
        uint4 mt = __ldg(&g_meta[w]);          // 1 sector: bm, dup, off
        unsigned slot = mt.z + __popc(mt.x & ((1u << b) - 1u));
        packed = (slot << 1) | ((mt.y >> b) & 1u);
    }
    packed = __shfl_sync(0xffffffffu, packed, lane >> 2);
    unsigned slot = packed >> 1, dup = packed & 1u;
    unsigned sub = lane & 3u;
    unsigned i = warpRow0 + (lane >> 2);

    float4 v = __ldcs((const float4*)vals + (size_t)i * 4 + sub);
    float* dst = out + (size_t)2 * NNZ + (size_t)slot * DENSE + sub * 4;
    if (dup) {
        atomicAdd(dst + 0, v.x); atomicAdd(dst + 1, v.y);
        atomicAdd(dst + 2, v.z); atomicAdd(dst + 3, v.w);
    } else {
        __stcs((float4*)dst, v);
    }
}

// ---------------------------------------------------------------------------
extern "C" void kernel_launch(void* const* d_in, const int* in_sizes, int n_in,
                              void* d_out, int out_size) {
    (void)in_sizes; (void)n_in; (void)out_size;
    const int*   idx  = (const int*)d_in[0];
    const float* vals = (const float*)d_in[1];
    float* out = (float*)d_out;

    unsigned zcnt = WORDS + SCAN_BLOCKS / 4 + 1;
    k_zero        <<<(zcnt + 255) / 256, 256>>>();
    k_mark        <<<NNZ / 256,          256>>>(idx);
    k_scan_compact<<<SCAN_BLOCKS,        256>>>(out);
    k_tail        <<<NNZ / 256,          256>>>(out);
    k_scatter     <<<NNZ * 4 / 256,      256>>>(idx, vals, out);
}

// round 4
// speedup vs baseline: 1.2590x; 1.1428x over previous
#include <cuda_runtime.h>

#define NNZ     4194304
#define DENSE   16
#define DIMLOG  13
#define DIMSZ   8192
#define WORDS   2097152u           // 2^26 cells / 32
#define SCAN_BLOCKS 2048
#define SCAN_WPT 4                 // words per thread in the scan kernel
#define STAGE_CAP 4096             // smem staging capacity (avg uniques/block ~1982)
#define MAIN_BLOCKS (NNZ * 4 / 256)
#define TAIL_BLOCKS 256

// Interleaved per-word metadata: x=occupancy bits, y=dup bits, z=exclusive
// slot offset of bit 0, w=pad. One 16B load (1 sector) serves the scatter.
__device__ __align__(16) uint4 g_meta[WORDS];
__device__ unsigned g_desc[SCAN_BLOCKS];   // decoupled-lookback descriptors
__device__ unsigned g_ticket;
__device__ unsigned g_total;

// ---------------------------------------------------------------------------
__device__ __forceinline__ unsigned block_exscan(unsigned v, unsigned& blocktotal) {
    __shared__ unsigned warp_sums[8];
    __shared__ unsigned warp_off[8];
    unsigned lane = threadIdx.x & 31u, wid = threadIdx.x >> 5;
    unsigned x = v;
#pragma unroll
    for (int d = 1; d < 32; d <<= 1) {
        unsigned y = __shfl_up_sync(0xffffffffu, x, d);
        if ((int)lane >= d) x += y;
    }
    if (lane == 31) warp_sums[wid] = x;
    __syncthreads();
    if (threadIdx.x < 8) {
        unsigned s = warp_sums[threadIdx.x];
        unsigned inc = s;
#pragma unroll
        for (int d = 1; d < 8; d <<= 1) {
            unsigned y = __shfl_up_sync(0xffu, inc, d);
            if ((int)threadIdx.x >= d) inc += y;
        }
        warp_off[threadIdx.x] = inc - s;
    }
    __syncthreads();
    blocktotal = warp_off[7] + warp_sums[7];
    return warp_off[wid] + (x - v);
}

// ---------------------------------------------------------------------------
// Z: zero metadata (32MB) + lookback descriptors + ticket
__global__ void k_zero() {
    unsigned i = blockIdx.x * 256u + threadIdx.x;
    uint4 z = {0u, 0u, 0u, 0u};
    if (i < WORDS)                      g_meta[i] = z;
    else if (i < WORDS + SCAN_BLOCKS/4) ((uint4*)g_desc)[i - WORDS] = z;
    else if (i == WORDS + SCAN_BLOCKS/4) g_ticket = 0u;
}

// B: mark occupancy + duplicate bits. 4 entries/thread, int4 loads.
__global__ void k_mark(const int* __restrict__ idx) {
    unsigned i = blockIdx.x * 256u + threadIdx.x;
    int4 r = __ldcs((const int4*)idx + i);
    int4 c = __ldcs((const int4*)(idx + NNZ) + i);
    unsigned f[4] = {
        ((unsigned)r.x << DIMLOG) | (unsigned)c.x,
        ((unsigned)r.y << DIMLOG) | (unsigned)c.y,
        ((unsigned)r.z << DIMLOG) | (unsigned)c.z,
        ((unsigned)r.w << DIMLOG) | (unsigned)c.w };
#pragma unroll
    for (int j = 0; j < 4; j++) {
        unsigned w = f[j] >> 5, m = 1u << (f[j] & 31u);
        unsigned old = atomicOr(&g_meta[w].x, m);
        if (old & m) atomicOr(&g_meta[w].y, m);
    }
}

// S: single-pass scan (decoupled lookback) + smem-staged compact of unique
//    indices + per-word offsets + dup-row zeroing + n_unique.
__global__ void k_scan_compact(float* __restrict__ out) {
    __shared__ unsigned sh_lbid, sh_prefix;
    __shared__ float s0[STAGE_CAP];
    __shared__ float s1[STAGE_CAP];
    unsigned tid = threadIdx.x;
    if (tid == 0) sh_lbid = atomicAdd(&g_ticket, 1u);
    __syncthreads();
    unsigned lbid = sh_lbid;
    unsigned base = lbid * (256u * SCAN_WPT) + tid * SCAN_WPT;

    uint4 mt[SCAN_WPT];
    unsigned s = 0;
#pragma unroll
    for (int j = 0; j < SCAN_WPT; j++) { mt[j] = g_meta[base + j]; s += __popc(mt[j].x); }
    unsigned tot;
    unsigned ex = block_exscan(s, tot);

    // Publish aggregate, warp-parallel lookback for exclusive prefix.
    if (tid < 32) {
        if (tid == 0) atomicExch(&g_desc[lbid], (tot << 2) | (lbid == 0 ? 2u : 1u));
        unsigned prefix = 0;
        if (lbid > 0) {
            int look = (int)lbid - 1;
            unsigned running = 0;
            while (true) {
                int j = look - 31 + (int)tid;
                unsigned d;
                if (j < 0) d = 2u;
                else {
                    do { d = *((volatile unsigned*)(g_desc + j)); } while ((d & 3u) == 0u);
                }
                unsigned ball = __ballot_sync(0xffffffffu, (d & 3u) == 2u);
                if (ball) {
                    int hi = 31 - __clz(ball);
                    unsigned contrib = ((int)tid >= hi) ? (d >> 2) : 0u;
                    running += __reduce_add_sync(0xffffffffu, contrib);
                    break;
                } else {
                    running += __reduce_add_sync(0xffffffffu, d >> 2);
                    look -= 32;
                }
            }
            prefix = running;
            if (tid == 0) atomicExch(&g_desc[lbid], ((prefix + tot) << 2) | 2u);
        }
        if (tid == 0) sh_prefix = prefix;
    }
    __syncthreads();

    unsigned prefix = sh_prefix;
    unsigned off = prefix + ex;
    if (lbid == SCAN_BLOCKS - 1 && tid == 0) {
        unsigned nu = prefix + tot;
        g_total = nu;
        out[(size_t)2 * NNZ + (size_t)NNZ * DENSE] = (float)nu;
    }

    float* out0 = out;
    float* out1 = out + NNZ;
    float* vout = out + (size_t)2 * NNZ;
    bool staged = (tot <= STAGE_CAP);

#pragma unroll
    for (int j = 0; j < SCAN_WPT; j++) {
        unsigned w = base + j;
        g_meta[w].z = off;                       // per-word exclusive offset
        unsigned bm = mt[j].x, dup = mt[j].y;
        unsigned o = off;
        unsigned v = bm;
        while (v) {
            unsigned b = (unsigned)__ffs(v) - 1u;
            v &= v - 1u;
            unsigned cell = (w << 5) | b;
            float rf = (float)(cell >> DIMLOG);
            float cf = (float)(cell & (DIMSZ - 1));
            if (staged) {
                unsigned lo = o - prefix;
                s0[lo] = rf; s1[lo] = cf;
            } else {
                __stcs(out0 + o, rf);
                __stcs(out1 + o, cf);
            }
            if ((dup >> b) & 1u) {               // pre-zero rows that accumulate
                float4* p = (float4*)(vout + (size_t)o * DENSE);
                float4 z = {0.f, 0.f, 0.f, 0.f};
                __stcs(p + 0, z); __stcs(p + 1, z); __stcs(p + 2, z); __stcs(p + 3, z);
            }
            o++;
        }
        off = o;
    }

    if (staged) {
        __syncthreads();
        for (unsigned i = tid; i < tot; i += 256u) {
            __stcs(out0 + prefix + i, s0[i]);
            __stcs(out1 + prefix + i, s1[i]);
        }
    }
}

// E: scatter values (4 threads/row) + fused tail fill (extra blocks).
__global__ void k_scatter(const int* __restrict__ idx,
                          const float* __restrict__ vals,
                          float* __restrict__ out) {
    if (blockIdx.x >= MAIN_BLOCKS) {
        // Tail: slots [g_total, NNZ) -> indices (8192, 0), zero values.
        unsigned nu = g_total;
        unsigned t0 = (blockIdx.x - MAIN_BLOCKS) * 256u + threadIdx.x;
        float4 z = {0.f, 0.f, 0.f, 0.f};
        for (unsigned slot = nu + t0; slot < NNZ; slot += TAIL_BLOCKS * 256u) {
            __stcs(out + slot, 8192.0f);
            __stcs(out + NNZ + slot, 0.0f);
            float4* v = (float4*)(out + (size_t)2 * NNZ + (size_t)slot * DENSE);
            __stcs(v + 0, z); __stcs(v + 1, z); __stcs(v + 2, z); __stcs(v + 3, z);
        }
        return;
    }

    unsigned t = blockIdx.x * 256u + threadIdx.x;
    unsigned lane = threadIdx.x & 31u;
    unsigned warpRow0 = (t & ~31u) >> 2;       // first of this warp's 8 rows

    unsigned packed = 0;
    if (lane < 8) {
        unsigned r = warpRow0 + lane;
        unsigned flat = ((unsigned)__ldg(idx + r) << DIMLOG) | (unsigned)__ldg(idx + NNZ + r);
        unsigned w = flat >> 5, b = flat & 31u;
        uint4 mt = __ldg(&g_meta[w]);          // 1 sector: bm, dup, off
        unsigned slot = mt.z + __popc(mt.x & ((1u << b) - 1u));
        packed = (slot << 1) | ((mt.y >> b) & 1u);
    }
    packed = __shfl_sync(0xffffffffu, packed, lane >> 2);
    unsigned slot = packed >> 1, dup = packed & 1u;
    unsigned sub = lane & 3u;
    unsigned i = warpRow0 + (lane >> 2);

    float4 v = __ldcs((const float4*)vals + (size_t)i * 4 + sub);
    float* dst = out + (size_t)2 * NNZ + (size_t)slot * DENSE + sub * 4;
    if (dup) {
        atomicAdd(dst + 0, v.x); atomicAdd(dst + 1, v.y);
        atomicAdd(dst + 2, v.z); atomicAdd(dst + 3, v.w);
    } else {
        __stcs((float4*)dst, v);
    }
}

// ---------------------------------------------------------------------------
extern "C" void kernel_launch(void* const* d_in, const int* in_sizes, int n_in,
                              void* d_out, int out_size) {
    (void)in_sizes; (void)n_in; (void)out_size;
    const int*   idx  = (const int*)d_in[0];
    const float* vals = (const float*)d_in[1];
    float* out = (float*)d_out;

    unsigned zcnt = WORDS + SCAN_BLOCKS / 4 + 1;
    k_zero        <<<(zcnt + 255) / 256, 256>>>();
    k_mark        <<<NNZ / 4 / 256,      256>>>(idx);
    k_scan_compact<<<SCAN_BLOCKS,        256>>>(out);
    k_scatter     <<<MAIN_BLOCKS + TAIL_BLOCKS, 256>>>(idx, vals, out);
}

// round 7
// speedup vs baseline: 1.3481x; 1.0708x over previous
#include <cuda_runtime.h>

#define NNZ     4194304
#define DENSE   16
#define DIMLOG  13
#define DIMSZ   8192
#define WORDS   2097152u           // 2^26 cells / 32
#define SCAN_BLOCKS 2048
#define SCAN_WPT 4
#define STAGE_CAP 4096
#define MAIN_BLOCKS (NNZ / 128)    // 16 rows/warp, 8 warps/block
#define TAIL_BLOCKS 256

// Compact mark-phase bits: x=occupancy, y=dup. 16MB, zeroed each run.
__device__ __align__(16) uint2 g_bits[WORDS];
// Scatter-phase metadata written by scan with full-line stores:
// x=occupancy bits, y=dup bits, z=exclusive slot offset of bit 0. Not zeroed.
__device__ __align__(16) uint4 g_meta[WORDS];
__device__ unsigned g_desc[SCAN_BLOCKS];
__device__ unsigned g_ticket;
__device__ unsigned g_total;

// ---------------------------------------------------------------------------
__device__ __forceinline__ unsigned block_exscan(unsigned v, unsigned& blocktotal) {
    __shared__ unsigned warp_sums[8];
    __shared__ unsigned warp_off[8];
    unsigned lane = threadIdx.x & 31u, wid = threadIdx.x >> 5;
    unsigned x = v;
#pragma unroll
    for (int d = 1; d < 32; d <<= 1) {
        unsigned y = __shfl_up_sync(0xffffffffu, x, d);
        if ((int)lane >= d) x += y;
    }
    if (lane == 31) warp_sums[wid] = x;
    __syncthreads();
    if (threadIdx.x < 8) {
        unsigned s = warp_sums[threadIdx.x];
        unsigned inc = s;
#pragma unroll
        for (int d = 1; d < 8; d <<= 1) {
            unsigned y = __shfl_up_sync(0xffu, inc, d);
            if ((int)threadIdx.x >= d) inc += y;
        }
        warp_off[threadIdx.x] = inc - s;
    }
    __syncthreads();
    blocktotal = warp_off[7] + warp_sums[7];
    return warp_off[wid] + (x - v);
}

// ---------------------------------------------------------------------------
// Z: zero mark bits (16MB) + lookback descriptors + ticket
__global__ void k_zero() {
    unsigned i = blockIdx.x * 256u + threadIdx.x;
    uint4 z = {0u, 0u, 0u, 0u};
    if (i < WORDS / 2)                        ((uint4*)g_bits)[i] = z;
    else if (i < WORDS/2 + SCAN_BLOCKS/4)     ((uint4*)g_desc)[i - WORDS/2] = z;
    else if (i == WORDS/2 + SCAN_BLOCKS/4)    g_ticket = 0u;
}

// B: mark occupancy + duplicate bits. 4 entries/thread, int4 loads.
__global__ void k_mark(const int* __restrict__ idx) {
    unsigned i = blockIdx.x * 256u + threadIdx.x;
    int4 r = __ldcs((const int4*)idx + i);
    int4 c = __ldcs((const int4*)(idx + NNZ) + i);
    unsigned f[4] = {
        ((unsigned)r.x << DIMLOG) | (unsigned)c.x,
        ((unsigned)r.y << DIMLOG) | (unsigned)c.y,
        ((unsigned)r.z << DIMLOG) | (unsigned)c.z,
        ((unsigned)r.w << DIMLOG) | (unsigned)c.w };
#pragma unroll
    for (int j = 0; j < 4; j++) {
        unsigned w = f[j] >> 5, m = 1u << (f[j] & 31u);
        unsigned old = atomicOr(&g_bits[w].x, m);
        if (old & m) atomicOr(&g_bits[w].y, m);
    }
}

// S: single-pass scan (decoupled lookback) + full-line meta writes +
//    smem-staged compact of unique indices + dup-row zeroing + n_unique.
__global__ void k_scan_compact(float* __restrict__ out) {
    __shared__ unsigned sh_lbid, sh_prefix;
    __shared__ float s0[STAGE_CAP];
    __shared__ float s1[STAGE_CAP];
    unsigned tid = threadIdx.x;
    if (tid == 0) sh_lbid = atomicAdd(&g_ticket, 1u);
    __syncthreads();
    unsigned lbid = sh_lbid;
    unsigned base = lbid * (256u * SCAN_WPT) + tid * SCAN_WPT;

    uint2 bd[SCAN_WPT];
    unsigned s = 0;
#pragma unroll
    for (int j = 0; j < SCAN_WPT; j++) { bd[j] = g_bits[base + j]; s += __popc(bd[j].x); }
    unsigned tot;
    unsigned ex = block_exscan(s, tot);

    if (tid < 32) {
        if (tid == 0) atomicExch(&g_desc[lbid], (tot << 2) | (lbid == 0 ? 2u : 1u));
        unsigned prefix = 0;
        if (lbid > 0) {
            int look = (int)lbid - 1;
            unsigned running = 0;
            while (true) {
                int j = look - 31 + (int)tid;
                unsigned d;
                if (j < 0) d = 2u;
                else {
                    do { d = *((volatile unsigned*)(g_desc + j)); } while ((d & 3u) == 0u);
                }
                unsigned ball = __ballot_sync(0xffffffffu, (d & 3u) == 2u);
                if (ball) {
                    int hi = 31 - __clz(ball);
                    unsigned contrib = ((int)tid >= hi) ? (d >> 2) : 0u;
                    running += __reduce_add_sync(0xffffffffu, contrib);
                    break;
                } else {
                    running += __reduce_add_sync(0xffffffffu, d >> 2);
                    look -= 32;
                }
            }
            prefix = running;
            if (tid == 0) atomicExch(&g_desc[lbid], ((prefix + tot) << 2) | 2u);
        }
        if (tid == 0) sh_prefix = prefix;
    }
    __syncthreads();

    unsigned prefix = sh_prefix;
    unsigned off = prefix + ex;
    if (lbid == SCAN_BLOCKS - 1 && tid == 0) {
        unsigned nu = prefix + tot;
        g_total = nu;
        out[(size_t)2 * NNZ + (size_t)NNZ * DENSE] = (float)nu;
    }

    float* out0 = out;
    float* out1 = out + NNZ;
    float* vout = out + (size_t)2 * NNZ;
    bool staged = (tot <= STAGE_CAP);

#pragma unroll
    for (int j = 0; j < SCAN_WPT; j++) {
        unsigned w = base + j;
        unsigned bm = bd[j].x, dup = bd[j].y;
        uint4 m4; m4.x = bm; m4.y = dup; m4.z = off; m4.w = 0u;
        g_meta[w] = m4;                          // full-line STG.128
        unsigned o = off;
        unsigned v = bm;
        while (v) {
            unsigned b = (unsigned)__ffs(v) - 1u;
            v &= v - 1u;
            unsigned cell = (w << 5) | b;
            float rf = (float)(cell >> DIMLOG);
            float cf = (float)(cell & (DIMSZ - 1));
            if (staged) {
                unsigned lo = o - prefix;
                s0[lo] = rf; s1[lo] = cf;
            } else {
                __stcs(out0 + o, rf);
                __stcs(out1 + o, cf);
            }
            if ((dup >> b) & 1u) {
                float4* p = (float4*)(vout + (size_t)o * DENSE);
                float4 z = {0.f, 0.f, 0.f, 0.f};
                __stcs(p + 0, z); __stcs(p + 1, z); __stcs(p + 2, z); __stcs(p + 3, z);
            }
            o++;
        }
        off = o;
    }

    if (staged) {
        __syncthreads();
        for (unsigned i = tid; i < tot; i += 256u) {
            __stcs(out0 + prefix + i, s0[i]);
            __stcs(out1 + prefix + i, s1[i]);
        }
    }
}

// E: scatter values. 16 rows/warp; lanes 0..15 resolve (slot,dup) per row,
// every lane then moves 32B (two independent float4s) -> doubled MLP,
// half as many idx->meta latency chains. Fused tail fill in extra blocks.
__global__ void k_scatter(const int* __restrict__ idx,
                          const float* __restrict__ vals,
                          float* __restrict__ out) {
    if (blockIdx.x >= MAIN_BLOCKS) {
        unsigned nu = g_total;
        unsigned t0 = (blockIdx.x - MAIN_BLOCKS) * 256u + threadIdx.x;
        float4 z = {0.f, 0.f, 0.f, 0.f};
        for (unsigned slot = nu + t0; slot < NNZ; slot += TAIL_BLOCKS * 256u) {
            __stcs(out + slot, 8192.0f);
            __stcs(out + NNZ + slot, 0.0f);
            float4* v = (float4*)(out + (size_t)2 * NNZ + (size_t)slot * DENSE);
            __stcs(v + 0, z); __stcs(v + 1, z); __stcs(v + 2, z); __stcs(v + 3, z);
        }
        return;
    }

    unsigned t = blockIdx.x * 256u + threadIdx.x;
    unsigned lane = threadIdx.x & 31u;
    unsigned warpRow0 = (t >> 5) * 16u;

    unsigned packed = 0;
    if (lane < 16) {
        unsigned r = warpRow0 + lane;
        unsigned flat = ((unsigned)__ldg(idx + r) << DIMLOG) | (unsigned)__ldg(idx + NNZ + r);
        unsigned w = flat >> 5, b = flat & 31u;
        uint4 mt = __ldg(&g_meta[w]);
        unsigned slot = mt.z + __popc(mt.x & ((1u << b) - 1u));
        packed = (slot << 1) | ((mt.y >> b) & 1u);
    }
    packed = __shfl_sync(0xffffffffu, packed, lane >> 1);
    unsigned slot = packed >> 1, dup = packed & 1u;
    unsigned sub = (lane & 1u) * 2u;               // quarters sub, sub+1
    unsigned i = warpRow0 + (lane >> 1);

    const float4* src = (const float4*)vals + (size_t)i * 4 + sub;
    float4 v0 = __ldcs(src + 0);
    float4 v1 = __ldcs(src + 1);
    float* dst = out + (size_t)2 * NNZ + (size_t)slot * DENSE + sub * 4;
    if (dup) {
        atomicAdd(dst + 0, v0.x); atomicAdd(dst + 1, v0.y);
        atomicAdd(dst + 2, v0.z); atomicAdd(dst + 3, v0.w);
        atomicAdd(dst + 4, v1.x); atomicAdd(dst + 5, v1.y);
        atomicAdd(dst + 6, v1.z); atomicAdd(dst + 7, v1.w);
    } else {
        __stcs((float4*)dst + 0, v0);
        __stcs((float4*)dst + 1, v1);
    }
}

// ---------------------------------------------------------------------------
extern "C" void kernel_launch(void* const* d_in, const int* in_sizes, int n_in,
                              void* d_out, int out_size) {
    (void)in_sizes; (void)n_in; (void)out_size;
    const int*   idx  = (const int*)d_in[0];
    const float* vals = (const float*)d_in[1];
    float* out = (float*)d_out;

    unsigned zcnt = WORDS / 2 + SCAN_BLOCKS / 4 + 1;
    k_zero        <<<(zcnt + 255) / 256, 256>>>();
    k_mark        <<<NNZ / 4 / 256,      256>>>(idx);
    k_scan_compact<<<SCAN_BLOCKS,        256>>>(out);
    k_scatter     <<<MAIN_BLOCKS + TAIL_BLOCKS, 256>>>(idx, vals, out);
}